// round 8
// baseline (speedup 1.0000x reference)
#include <cuda_runtime.h>
#include <cuda_bf16.h>
#include <cstdint>

#define NT   32768
#define NE   8192
#define DIM  64
#define BM   128      // tokens per CTA
#define BN   128      // codes per K-tile iteration (64 iterations)
#define INT_NEG (-2147483648)

// ---------------------------------------------------------------------------
// Static device scratch
// ---------------------------------------------------------------------------
__device__ int8_t g_xi8[NT * DIM];    // per-token-scaled int8 x
__device__ int8_t g_ci8[NE * DIM];    // globally-scaled int8 codebook
__device__ float  g_xnorm[NT];
__device__ double g_lsum[256];

__device__ __forceinline__ uint32_t smem_u32(const void* p) {
    uint32_t a;
    asm("{ .reg .u64 t; cvta.to.shared.u64 t, %1; cvt.u32.u64 %0, t; }"
        : "=r"(a) : "l"(p));
    return a;
}
__device__ __forceinline__ void ldsm_x4(uint32_t& r0, uint32_t& r1,
                                        uint32_t& r2, uint32_t& r3, uint32_t a) {
    asm volatile("ldmatrix.sync.aligned.m8n8.x4.shared.b16 {%0,%1,%2,%3}, [%4];"
                 : "=r"(r0), "=r"(r1), "=r"(r2), "=r"(r3) : "r"(a));
}
__device__ __forceinline__ void mma_s8(int* c, const uint32_t* a,
                                       uint32_t b0, uint32_t b1) {
    asm volatile(
        "mma.sync.aligned.m16n8k32.row.col.s32.s8.s8.s32 "
        "{%0,%1,%2,%3}, {%4,%5,%6,%7}, {%8,%9}, {%0,%1,%2,%3};"
        : "+r"(c[0]), "+r"(c[1]), "+r"(c[2]), "+r"(c[3])
        : "r"(a[0]), "r"(a[1]), "r"(a[2]), "r"(a[3]), "r"(b0), "r"(b1));
}
__device__ __forceinline__ void cp16(uint32_t dst, const void* src, uint32_t sz) {
    asm volatile("cp.async.cg.shared.global [%0], [%1], 16, %2;"
                 :: "r"(dst), "l"(src), "r"(sz) : "memory");
}
#define CP_COMMIT() asm volatile("cp.async.commit_group;" ::: "memory")
#define CP_WAIT(n)  asm volatile("cp.async.wait_group %0;" :: "n"(n) : "memory")

// 64B-row swizzle: 16B-chunk col c (0..3) XORed with (row>>1)&3 makes every
// 8-row ldmatrix access hit 8 distinct 16B bank-groups.
#define SW64(row, c) (((row) * 64) + ((((c) ^ (((row) >> 1) & 3))) << 4))

// ---------------------------------------------------------------------------
// Prep: int8 quantization + exact fp32 token norms (fmaf, d ascending)
// ---------------------------------------------------------------------------
__global__ void prep_x(const float* __restrict__ x) {
    int t = blockIdx.x * blockDim.x + threadIdx.x;
    float v[DIM];
#pragma unroll
    for (int i = 0; i < 16; i++)
        *(float4*)&v[i * 4] = ((const float4*)(x + t * DIM))[i];
    float s = 0.0f, mx = 0.0f;
#pragma unroll
    for (int d = 0; d < DIM; d++) {
        s  = fmaf(v[d], v[d], s);
        mx = fmaxf(mx, fabsf(v[d]));
    }
    g_xnorm[t] = s;
    float xscale = 127.0f / fmaxf(mx, 1e-30f);   // per-token: monotonic per token
    char q[DIM];
#pragma unroll
    for (int d = 0; d < DIM; d++) {
        int qi = __float2int_rn(v[d] * xscale);
        qi = max(-127, min(127, qi));
        q[d] = (char)qi;
    }
#pragma unroll
    for (int i = 0; i < 4; i++)
        ((uint4*)g_xi8)[t * 4 + i] = *(uint4*)&q[i * 16];
}

__global__ void prep_c(const float* __restrict__ cb) {
    int t = blockIdx.x * blockDim.x + threadIdx.x;
    float v[DIM];
#pragma unroll
    for (int i = 0; i < 16; i++)
        *(float4*)&v[i * 4] = ((const float4*)(cb + t * DIM))[i];
    const float cscale = 127.0f * 8192.0f;       // codebook in [-1/8192, 1/8192]
    char q[DIM];
#pragma unroll
    for (int d = 0; d < DIM; d++) {
        int qi = __float2int_rn(v[d] * cscale);
        qi = max(-127, min(127, qi));
        q[d] = (char)qi;
    }
#pragma unroll
    for (int i = 0; i < 4; i++)
        ((uint4*)g_ci8)[t * 4 + i] = *(uint4*)&q[i * 16];
}

// ---------------------------------------------------------------------------
// Main fused kernel: int8 IMMA screen (int32 scores, per-token monotonic),
// per-thread top-4, exact fp32 rescue, fused gather + loss epilogue.
// 8 warps; warp = 16 token rows x 128 cols. A fragments register-resident.
// ---------------------------------------------------------------------------
__global__ void __launch_bounds__(256, 2)
vq_mma(const float* __restrict__ x, const float* __restrict__ cb,
       const int* __restrict__ ps, const int* __restrict__ pe,
       float* __restrict__ out) {
    __shared__ __align__(16) char  smA[8192];        // A int8: 128 rows x 64B
    __shared__ __align__(16) char  smB[3][8192];     // B int8 ring: 128 x 64B
    __shared__ int    smIdx[BM];
    __shared__ double smRed[256];

    uint32_t aB  = smem_u32(smA);
    uint32_t bB0 = smem_u32(&smB[0][0]);
    int tid  = threadIdx.x;
    int wid  = tid >> 5, lane = tid & 31;
    int start = *ps;
    int K     = *pe - start;
    int bm    = blockIdx.x * BM;

    // ---- Load A tile (x int8): 128 rows x 4 16B-chunks, swizzled ----
#pragma unroll
    for (int u = 0; u < 2; u++) {
        int ch  = u * 256 + tid;                     // 512 chunks
        int row = ch >> 2, c = ch & 3;
        *(uint4*)(smA + SW64(row, c)) = ((const uint4*)g_xi8)[(bm + row) * 4 + c];
    }

    // ---- Prefetch B tile 0 into ring stage 0 ----
    int ntiles = (K + BN - 1) / BN;
#pragma unroll
    for (int u = 0; u < 2; u++) {
        int ch  = u * 256 + tid;
        int row = ch >> 2, c = ch & 3;
        int ok  = (row < K);
        int code = start + (ok ? row : 0);
        cp16(bB0 + (uint32_t)SW64(row, c),
             (const char*)g_ci8 + (size_t)code * 64 + c * 16, ok ? 16u : 0u);
    }
    CP_COMMIT();
    __syncthreads();

    // ---- Hoist A fragments: 2 k32-chunks x 4 regs (invariant) ----
    uint32_t afr[2][4];
    {
        int arow = wid * 16 + ((lane >> 3) & 1) * 8 + (lane & 7);
#pragma unroll
        for (int q = 0; q < 2; q++) {
            int c = 2 * q + (lane >> 4);
            ldsm_x4(afr[q][0], afr[q][1], afr[q][2], afr[q][3],
                    aB + (uint32_t)SW64(arow, c));
        }
    }

    // Per-thread top-4 (int32 screen scores) for the 2 owned token rows.
    int bs[2][4], bk[2][4];
#pragma unroll
    for (int t = 0; t < 2; t++)
#pragma unroll
        for (int j = 0; j < 4; j++) { bs[t][j] = INT_NEG; bk[t][j] = 0; }

    int cnb = 2 * (lane & 3);
    int bl8 = lane & 7, blc = lane >> 3;             // B ldsm addressing

    for (int it = 0; it < ntiles; it++) {
        int kb = it * BN;
        if (it + 1 < ntiles) {
            uint32_t bN = bB0 + (uint32_t)(((it + 1) % 3) * 8192);
            int kb2 = kb + BN;
#pragma unroll
            for (int u = 0; u < 2; u++) {
                int ch  = u * 256 + tid;
                int row = ch >> 2, c = ch & 3;
                int ok  = (kb2 + row < K);
                int code = start + (ok ? kb2 + row : 0);
                cp16(bN + (uint32_t)SW64(row, c),
                     (const char*)g_ci8 + (size_t)code * 64 + c * 16,
                     ok ? 16u : 0u);
            }
            CP_COMMIT();
            CP_WAIT(1);
        } else {
            CP_WAIT(0);
        }
        __syncthreads();     // single barrier per iter; 3-stage ring makes WAR safe

        uint32_t bS = bB0 + (uint32_t)((it % 3) * 8192);
        bool full = (kb + BN <= K);

#pragma unroll
        for (int g = 0; g < 16; g++) {               // 16 n8 groups, full K=64 each
            int brow = g * 8 + bl8;
            uint32_t r0, r1, r2, r3;
            ldsm_x4(r0, r1, r2, r3, bS + (uint32_t)SW64(brow, blc));
            int d[4] = {0, 0, 0, 0};
            mma_s8(d, afr[0], r0, r1);               // k 0..31
            mma_s8(d, afr[1], r2, r3);               // k 32..63
            // Scan: tt0 owns d0,d1 (row lane>>2); tt1 owns d2,d3 (row+8)
#pragma unroll
            for (int tt = 0; tt < 2; tt++) {
                int v0 = d[tt * 2], v1 = d[tt * 2 + 1];
                if (max(v0, v1) > bs[tt][3]) {       // rare after warm-up
#pragma unroll
                    for (int e = 0; e < 2; e++) {
                        int s = e ? v1 : v0;
                        if (s > bs[tt][3]) {
                            int key = kb + g * 8 + cnb + e;
                            if (full || key < K) {
                                if (s > bs[tt][1]) {
                                    if (s > bs[tt][0]) {
                                        bs[tt][3] = bs[tt][2]; bk[tt][3] = bk[tt][2];
                                        bs[tt][2] = bs[tt][1]; bk[tt][2] = bk[tt][1];
                                        bs[tt][1] = bs[tt][0]; bk[tt][1] = bk[tt][0];
                                        bs[tt][0] = s;         bk[tt][0] = key;
                                    } else {
                                        bs[tt][3] = bs[tt][2]; bk[tt][3] = bk[tt][2];
                                        bs[tt][2] = bs[tt][1]; bk[tt][2] = bk[tt][1];
                                        bs[tt][1] = s;         bk[tt][1] = key;
                                    }
                                } else if (s > bs[tt][2]) {
                                    bs[tt][3] = bs[tt][2]; bk[tt][3] = bk[tt][2];
                                    bs[tt][2] = s;         bk[tt][2] = key;
                                } else {
                                    bs[tt][3] = s;         bk[tt][3] = key;
                                }
                            }
                        }
                    }
                }
            }
        }
    }

    // ---- Exact fp32 rescue (identical numerics to validated kernels) ----
#pragma unroll
    for (int tt = 0; tt < 2; tt++) {
        int rowl  = wid * 16 + tt * 8 + (lane >> 2);
        int token = bm + rowl;
        const float* xr = x + (size_t)token * DIM;
        float xn = g_xnorm[token];
        float bestq = 3.4e38f;
        int   besti = 2147483647;
#pragma unroll
        for (int cnd = 0; cnd < 4; cnd++) {
            if (bs[tt][cnd] == INT_NEG) continue;
            int gi = bk[tt][cnd] + start;
            const float* cr = cb + (size_t)gi * DIM;
            float s = 0.0f;
#pragma unroll
            for (int d = 0; d < DIM; d++) s = fmaf(xr[d], cr[d], s);
            float q = fmaf(-2.0f, s, xn);
            if (q < bestq || (q == bestq && gi < besti)) { bestq = q; besti = gi; }
        }
#pragma unroll
        for (int m = 1; m <= 2; m <<= 1) {
            float oq = __shfl_xor_sync(0xffffffffu, bestq, m);
            int   oi = __shfl_xor_sync(0xffffffffu, besti, m);
            if (oq < bestq || (oq == bestq && oi < besti)) { bestq = oq; besti = oi; }
        }
        if ((lane & 3) == 0) smIdx[rowl] = besti;
    }
    __syncthreads();

    // ---- Fused epilogue: gather + straight-through out + loss partial ----
    // out layout: [0, NT*DIM) x_q_st | [NT*DIM] loss | [NT*DIM+1, +NT) indices
    double lsum = 0.0;
#pragma unroll
    for (int u = 0; u < 32; u++) {
        int e  = u * 256 + tid;
        int tl = e >> 6;
        int d  = e & 63;
        int idx = smIdx[tl];
        int ge  = (bm + tl) * DIM + d;
        float xv = x[ge];
        float xq = cb[(size_t)idx * DIM + d];
        float dq = __fsub_rn(xq, xv);
        out[ge]  = __fadd_rn(xv, dq);
        lsum += (double)dq * (double)dq;
        if (d == 0) out[NT * DIM + 1 + bm + tl] = (float)idx;
    }
    smRed[tid] = lsum;
    __syncthreads();
    for (int w = 128; w > 0; w >>= 1) {
        if (tid < w) smRed[tid] += smRed[tid + w];
        __syncthreads();
    }
    if (tid == 0) g_lsum[blockIdx.x] = smRed[0];
}

// ---------------------------------------------------------------------------
__global__ void loss_k(float* __restrict__ out) {
    __shared__ double red[256];
    int tid = threadIdx.x;
    red[tid] = g_lsum[tid];
    __syncthreads();
    for (int w = 128; w > 0; w >>= 1) {
        if (tid < w) red[tid] += red[tid + w];
        __syncthreads();
    }
    if (tid == 0) {
        double m = red[0] / (double)(NT * DIM);
        out[NT * DIM] = (float)(m + 0.25 * m);   // codebook + BETA*commitment
    }
}

// ---------------------------------------------------------------------------
extern "C" void kernel_launch(void* const* d_in, const int* in_sizes, int n_in,
                              void* d_out, int out_size) {
    const float* x  = (const float*)d_in[0];
    const float* cb = (const float*)d_in[1];
    const int* ps   = (const int*)d_in[2];
    const int* pe   = (const int*)d_in[3];
    float* out      = (float*)d_out;

    prep_x<<<NT / 256, 256>>>(x);
    prep_c<<<NE / 256, 256>>>(cb);
    vq_mma<<<NT / BM, 256>>>(x, cb, ps, pe, out);
    loss_k<<<1, 256>>>(out);
}